// round 2
// baseline (speedup 1.0000x reference)
#include <cuda_runtime.h>

// Problem constants (fixed by the reference)
#define RAYS   32768
#define NS     128      // samples per ray
#define IN_DIR 16
#define HID    8

// Inputs (metadata order):
//  d_in[0] x          int32  [B, N, 2]
//  d_in[1] d          float  [B, 16]
//  d_in[2] gridWeight float  [16777216, 4]
//  d_in[3] W0         float  [22, 8]
//  d_in[4] W1         float  [8, 3]
// Output: sigma [B, N] then rgb [B, 3], concatenated, float32.

// Random 16B gathers into a 256MB table: the default 128B L2 miss fetch
// granularity overfetches 4-8x. Request 32B sector fills. Runs at program
// start (before harness mem checkpoints, outside graph capture).
struct _L2GranInit {
    _L2GranInit() { cudaDeviceSetLimit(cudaLimitMaxL2FetchGranularity, 32); }
};
static _L2GranInit _l2_gran_init;

__global__ __launch_bounds__(NS) void surf_kernel(
    const int2*  __restrict__ x,        // [B*N] pairs
    const float* __restrict__ d,        // [B,16]
    const float4* __restrict__ grid,    // [TABLE] rows of 4
    const float* __restrict__ W0,       // [22,8] row-major
    const float* __restrict__ W1,       // [8,3]  row-major
    float* __restrict__ out_sigma,      // [B,N]
    float* __restrict__ out_rgb)        // [B,3]
{
    const int b    = blockIdx.x;
    const int n    = threadIdx.x;       // 0..127
    const int lane = n & 31;
    const int wid  = n >> 5;

    __shared__ float sW0g[6][HID];      // W0 rows 16..21 (geo part)
    __shared__ float sW1[HID][3];
    __shared__ float sBase[HID];        // d-row @ W0[0:16] (shared by all samples of ray)
    __shared__ float sWarpProd[4];
    __shared__ float sRgb[4][3];

    // ---- issue the random gathers FIRST (they dominate; overlap with setup) ----
    const int2  idx = __ldcs(x + (size_t)b * NS + n);   // streaming: don't pollute L2
    const float4 g0 = __ldg(grid + idx.x);
    const float4 g1 = __ldg(grid + idx.y);

    // Cooperative small loads / per-ray base MLP term (overlaps gather latency)
    if (n < 48) {
        sW0g[n >> 3][n & 7] = W0[(16 + (n >> 3)) * HID + (n & 7)];
    } else if (n >= 64 && n < 88) {
        int t = n - 64;
        sW1[t / 3][t % 3] = W1[t];
    } else if (n >= 96 && n < 96 + HID) {
        int j = n - 96;
        const float* dd = d + (size_t)b * IN_DIR;
        float acc = 0.f;
        #pragma unroll
        for (int k = 0; k < IN_DIR; ++k) acc = fmaf(dd[k], W0[k * HID + j], acc);
        sBase[j] = acc;
    }
    __syncthreads();

    const float sig = 1.f / (1.f + __expf(-(g0.x * g1.x)));
    __stcs(out_sigma + (size_t)b * NS + n, sig);        // streaming store

    // ---- per-sample MLP: geo(6) @ W0g + base, relu, @ W1, sigmoid ----
    float h[HID];
    #pragma unroll
    for (int j = 0; j < HID; ++j) {
        float a = sBase[j];
        a = fmaf(g0.y, sW0g[0][j], a);
        a = fmaf(g0.z, sW0g[1][j], a);
        a = fmaf(g0.w, sW0g[2][j], a);
        a = fmaf(g1.y, sW0g[3][j], a);
        a = fmaf(g1.z, sW0g[4][j], a);
        a = fmaf(g1.w, sW0g[5][j], a);
        h[j] = fmaxf(a, 0.f);
    }
    float c0 = 0.f, c1 = 0.f, c2 = 0.f;
    #pragma unroll
    for (int j = 0; j < HID; ++j) {
        c0 = fmaf(h[j], sW1[j][0], c0);
        c1 = fmaf(h[j], sW1[j][1], c1);
        c2 = fmaf(h[j], sW1[j][2], c2);
    }
    c0 = 1.f / (1.f + __expf(-c0));
    c1 = 1.f / (1.f + __expf(-c1));
    c2 = 1.f / (1.f + __expf(-c2));

    // ---- exclusive prefix product of (1 - sigma) across the 128 samples ----
    float p = 1.f - sig;
    #pragma unroll
    for (int off = 1; off < 32; off <<= 1) {
        float v = __shfl_up_sync(0xffffffffu, p, off);
        if (lane >= off) p *= v;
    }
    if (lane == 31) sWarpProd[wid] = p;           // inclusive warp total
    float pe = __shfl_up_sync(0xffffffffu, p, 1); // exclusive within warp
    if (lane == 0) pe = 1.f;
    __syncthreads();
    float prefix = 1.f;
    #pragma unroll
    for (int wnum = 0; wnum < 4; ++wnum)
        if (wnum < wid) prefix *= sWarpProd[wnum];
    const float T = pe * prefix;
    const float w = T * sig;

    // ---- rgb = sum_n w * color ----
    float r0 = w * c0, r1 = w * c1, r2 = w * c2;
    #pragma unroll
    for (int off = 16; off > 0; off >>= 1) {
        r0 += __shfl_down_sync(0xffffffffu, r0, off);
        r1 += __shfl_down_sync(0xffffffffu, r1, off);
        r2 += __shfl_down_sync(0xffffffffu, r2, off);
    }
    if (lane == 0) { sRgb[wid][0] = r0; sRgb[wid][1] = r1; sRgb[wid][2] = r2; }
    __syncthreads();
    if (n == 0) {
        float a0 = sRgb[0][0] + sRgb[1][0] + sRgb[2][0] + sRgb[3][0];
        float a1 = sRgb[0][1] + sRgb[1][1] + sRgb[2][1] + sRgb[3][1];
        float a2 = sRgb[0][2] + sRgb[1][2] + sRgb[2][2] + sRgb[3][2];
        float* o = out_rgb + (size_t)b * 3;
        o[0] = a0; o[1] = a1; o[2] = a2;
    }
}

extern "C" void kernel_launch(void* const* d_in, const int* in_sizes, int n_in,
                              void* d_out, int out_size) {
    const int2*  x    = (const int2*)d_in[0];
    const float* d    = (const float*)d_in[1];
    const float4* gw  = (const float4*)d_in[2];
    const float* W0   = (const float*)d_in[3];
    const float* W1   = (const float*)d_in[4];
    float* out_sigma  = (float*)d_out;
    float* out_rgb    = out_sigma + (size_t)RAYS * NS;

    surf_kernel<<<RAYS, NS>>>(x, d, gw, W0, W1, out_sigma, out_rgb);
}

// round 3
// speedup vs baseline: 1.1716x; 1.1716x over previous
#include <cuda_runtime.h>

// Problem constants (fixed by the reference)
#define RAYS   32768
#define NS     128      // samples per ray
#define IN_DIR 16
#define HID    8

// Inputs (metadata order):
//  d_in[0] x          int32  [B, N, 2]
//  d_in[1] d          float  [B, 16]
//  d_in[2] gridWeight float  [16777216, 4]
//  d_in[3] W0         float  [22, 8]
//  d_in[4] W1         float  [8, 3]
// Output: sigma [B, N] then rgb [B, 3], concatenated, float32.
//
// R2 lesson: 32B L2 fetch granularity killed accidental 128B-line reuse
// (avg 4 touches/line) and made the kernel latency-bound. Default 128B
// granularity restored; instead we raise memory-level parallelism:
// one block = 2 rays => 4 independent table gathers per thread.

__global__ __launch_bounds__(128) void surf_kernel(
    const int2*  __restrict__ x,        // [B*N] pairs
    const float* __restrict__ d,        // [B,16]
    const float4* __restrict__ grid,    // [TABLE] rows of 4
    const float* __restrict__ W0,       // [22,8] row-major
    const float* __restrict__ W1,       // [8,3]  row-major
    float* __restrict__ out_sigma,      // [B,N]
    float* __restrict__ out_rgb)        // [B,3]
{
    const int b0   = blockIdx.x * 2;    // this block handles rays b0, b0+1
    const int n    = threadIdx.x;       // 0..127 = sample index
    const int lane = n & 31;
    const int wid  = n >> 5;

    __shared__ float sW0g[6][HID];      // W0 rows 16..21 (geo part)
    __shared__ float sW1[HID][3];
    __shared__ float sBase[2][HID];     // per-ray d-row @ W0[0:16]
    __shared__ float sWarpProd[2][4];
    __shared__ float sRgb[2][4][3];

    // ---- issue all 4 random gathers FIRST (the bottleneck) ----
    const int2 idxA = __ldcs(x + (size_t)b0 * NS + n);
    const int2 idxB = __ldcs(x + (size_t)(b0 + 1) * NS + n);
    const float4 gA0 = __ldg(grid + idxA.x);
    const float4 gA1 = __ldg(grid + idxA.y);
    const float4 gB0 = __ldg(grid + idxB.x);
    const float4 gB1 = __ldg(grid + idxB.y);

    // Cooperative setup overlaps gather latency
    if (n < 48) {
        sW0g[n >> 3][n & 7] = W0[(16 + (n >> 3)) * HID + (n & 7)];
    } else if (n >= 64 && n < 88) {
        int t = n - 64;
        sW1[t / 3][t % 3] = W1[t];
    } else if (n >= 96 && n < 96 + 2 * HID) {
        int t = n - 96;          // 0..15
        int r = t >> 3;          // ray select
        int j = t & 7;
        const float* dd = d + (size_t)(b0 + r) * IN_DIR;
        float acc = 0.f;
        #pragma unroll
        for (int k = 0; k < IN_DIR; ++k) acc = fmaf(dd[k], W0[k * HID + j], acc);
        sBase[r][j] = acc;
    }
    __syncthreads();

    float sig[2], c[2][3];
    #pragma unroll
    for (int r = 0; r < 2; ++r) {
        const float4 g0 = r ? gB0 : gA0;
        const float4 g1 = r ? gB1 : gA1;
        sig[r] = 1.f / (1.f + __expf(-(g0.x * g1.x)));
        __stcs(out_sigma + (size_t)(b0 + r) * NS + n, sig[r]);

        float h[HID];
        #pragma unroll
        for (int j = 0; j < HID; ++j) {
            float a = sBase[r][j];
            a = fmaf(g0.y, sW0g[0][j], a);
            a = fmaf(g0.z, sW0g[1][j], a);
            a = fmaf(g0.w, sW0g[2][j], a);
            a = fmaf(g1.y, sW0g[3][j], a);
            a = fmaf(g1.z, sW0g[4][j], a);
            a = fmaf(g1.w, sW0g[5][j], a);
            h[j] = fmaxf(a, 0.f);
        }
        float c0 = 0.f, c1 = 0.f, c2 = 0.f;
        #pragma unroll
        for (int j = 0; j < HID; ++j) {
            c0 = fmaf(h[j], sW1[j][0], c0);
            c1 = fmaf(h[j], sW1[j][1], c1);
            c2 = fmaf(h[j], sW1[j][2], c2);
        }
        c[r][0] = 1.f / (1.f + __expf(-c0));
        c[r][1] = 1.f / (1.f + __expf(-c1));
        c[r][2] = 1.f / (1.f + __expf(-c2));
    }

    // ---- exclusive prefix product of (1 - sigma) per ray ----
    float pe[2];
    #pragma unroll
    for (int r = 0; r < 2; ++r) {
        float p = 1.f - sig[r];
        #pragma unroll
        for (int off = 1; off < 32; off <<= 1) {
            float v = __shfl_up_sync(0xffffffffu, p, off);
            if (lane >= off) p *= v;
        }
        if (lane == 31) sWarpProd[r][wid] = p;         // inclusive warp total
        pe[r] = __shfl_up_sync(0xffffffffu, p, 1);     // exclusive within warp
        if (lane == 0) pe[r] = 1.f;
    }
    __syncthreads();

    #pragma unroll
    for (int r = 0; r < 2; ++r) {
        float prefix = 1.f;
        #pragma unroll
        for (int wnum = 0; wnum < 4; ++wnum)
            if (wnum < wid) prefix *= sWarpProd[r][wnum];
        const float w = pe[r] * prefix * sig[r];

        float r0 = w * c[r][0], r1 = w * c[r][1], r2 = w * c[r][2];
        #pragma unroll
        for (int off = 16; off > 0; off >>= 1) {
            r0 += __shfl_down_sync(0xffffffffu, r0, off);
            r1 += __shfl_down_sync(0xffffffffu, r1, off);
            r2 += __shfl_down_sync(0xffffffffu, r2, off);
        }
        if (lane == 0) { sRgb[r][wid][0] = r0; sRgb[r][wid][1] = r1; sRgb[r][wid][2] = r2; }
    }
    __syncthreads();

    if (n < 2) {   // thread 0 -> ray b0, thread 1 -> ray b0+1
        float a0 = sRgb[n][0][0] + sRgb[n][1][0] + sRgb[n][2][0] + sRgb[n][3][0];
        float a1 = sRgb[n][0][1] + sRgb[n][1][1] + sRgb[n][2][1] + sRgb[n][3][1];
        float a2 = sRgb[n][0][2] + sRgb[n][1][2] + sRgb[n][2][2] + sRgb[n][3][2];
        float* o = out_rgb + (size_t)(b0 + n) * 3;
        o[0] = a0; o[1] = a1; o[2] = a2;
    }
}

extern "C" void kernel_launch(void* const* d_in, const int* in_sizes, int n_in,
                              void* d_out, int out_size) {
    const int2*  x    = (const int2*)d_in[0];
    const float* d    = (const float*)d_in[1];
    const float4* gw  = (const float4*)d_in[2];
    const float* W0   = (const float*)d_in[3];
    const float* W1   = (const float*)d_in[4];
    float* out_sigma  = (float*)d_out;
    float* out_rgb    = out_sigma + (size_t)RAYS * NS;

    surf_kernel<<<RAYS / 2, 128>>>(x, d, gw, W0, W1, out_sigma, out_rgb);
}